// round 2
// baseline (speedup 1.0000x reference)
#include <cuda_runtime.h>
#include <cstdint>

#define B_ 256
#define T_ 2048
#define I_ 50
#define H_ 116
#define O_ 50

typedef unsigned long long u64;

// ---------------- packed f32x2 helpers (Blackwell) ----------------
__device__ __forceinline__ u64 fma2(u64 a, u64 b, u64 c) {
    u64 d;
    asm("fma.rn.f32x2 %0, %1, %2, %3;" : "=l"(d) : "l"(a), "l"(b), "l"(c));
    return d;
}
__device__ __forceinline__ u64 add2(u64 a, u64 b) {
    u64 d;
    asm("add.rn.f32x2 %0, %1, %2;" : "=l"(d) : "l"(a), "l"(b));
    return d;
}
__device__ __forceinline__ float pair_sum(u64 a) {
    float lo = __uint_as_float((unsigned)(a & 0xFFFFFFFFull));
    float hi = __uint_as_float((unsigned)(a >> 32));
    return lo + hi;
}
__device__ __forceinline__ void cp8(void* smem, const void* gmem) {
    unsigned s = (unsigned)__cvta_generic_to_shared(smem);
    asm volatile("cp.async.ca.shared.global [%0], [%1], 8;" :: "r"(s), "l"(gmem));
}

// ---------------- Fused kernel: input-proj + ReLU recurrence + FC ----------
// 128 CTAs x 256 threads. CTA handles batch rows 2*blk and 2*blk+1.
// Per 128-thread half (one batch row):
//   lanes [0,115]  : compute h[j] each step (weights register-resident)
//   lanes [0,49]   : ALSO compute out[b, t-1, lane] from h(t) (lag-1 FC)
//   lanes [116,127]: prefetch x via cp.async (3-step lead, 4-slot ring)
__global__ void __launch_bounds__(256, 1) rnn_fused_kernel(
    const float* __restrict__ x,
    const float* __restrict__ W_ih,
    const float* __restrict__ b_ih,
    const float* __restrict__ W_hh,
    const float* __restrict__ b_hh,
    const float* __restrict__ W_fc,
    const float* __restrict__ b_fc,
    float* __restrict__ out)
{
    __shared__ __align__(16) float h_buf[2][2][128];   // [pingpong][row][j]
    __shared__ __align__(16) float x_buf[4][2][56];    // 4-slot ring, 50 used
    __shared__ __align__(16) float wfc_s[O_ * H_];     // 23.2 KB

    const int tid  = threadIdx.x;
    const int r    = tid >> 7;        // which batch row of the CTA
    const int lane = tid & 127;
    const int b    = blockIdx.x * 2 + r;
    const bool is_j  = (lane < H_);
    const bool is_fc = (lane < O_);   // implies is_j
    const int j = lane;

    // Stage W_fc into shared (rows contiguous: o*116 floats; stride = 29
    // float4s, 29 coprime 32 -> conflict-free LDS.128 across lanes)
    {
        const float4* src = reinterpret_cast<const float4*>(W_fc);
        float4* dst = reinterpret_cast<float4*>(wfc_s);
        for (int i = tid; i < (O_ * H_) / 4; i += 256) dst[i] = src[i];
    }

    // Per-thread register-resident weight rows (as f32 pairs)
    u64 wih[25];
    u64 whh[58];
    float bias = 0.f, bfc = 0.f;
    if (is_j) {
        const u64* p1 = reinterpret_cast<const u64*>(W_ih + j * I_);
        #pragma unroll
        for (int q = 0; q < 25; q++) wih[q] = p1[q];
        const u64* p2 = reinterpret_cast<const u64*>(W_hh + j * H_);
        #pragma unroll
        for (int q = 0; q < 58; q++) whh[q] = p2[q];
        bias = b_ih[j] + b_hh[j];
        h_buf[0][r][j] = 0.f;          // h0 = 0
        if (is_fc) bfc = b_fc[lane];
    }

    const float* xb = x + (size_t)b * T_ * I_;
    const int u = lane - H_;           // loader index 0..11

    // Prologue: prefetch x for t = 0,1,2 (one cp.async group per timestep)
    if (!is_j) {
        #pragma unroll
        for (int s = 0; s < 3; s++) {
            cp8(&x_buf[s][r][2 * u],        xb + s * I_ + 2 * u);
            cp8(&x_buf[s][r][2 * (u + 12)], xb + s * I_ + 2 * (u + 12));
            if (u == 0) cp8(&x_buf[s][r][48], xb + s * I_ + 48);
            asm volatile("cp.async.commit_group;");
        }
        asm volatile("cp.async.wait_group 2;");  // slot 0 complete
    }
    __syncthreads();   // covers wfc_s, h0, x slot 0

    float* out_b = out + (size_t)b * T_ * O_ + lane;   // (fc lanes)
    const int bar_id = r + 1;
    int p = 0;
    for (int t = 0; t < T_; t++) {
        if (is_j) {
            const float* hrow = h_buf[p][r];   // = h(t), complete
            const ulonglong2* hv = reinterpret_cast<const ulonglong2*>(hrow);

            // ---- FC for out[b, t-1, :] from h(t)  (independent of h chain)
            if (is_fc && t > 0) {
                const ulonglong2* wv =
                    reinterpret_cast<const ulonglong2*>(wfc_s + lane * H_);
                u64 f0 = 0, f1 = 0, f2 = 0, f3 = 0;
                #pragma unroll
                for (int q = 0; q < 14; q++) {
                    ulonglong2 w0 = wv[2 * q],     hA = hv[2 * q];
                    ulonglong2 w1 = wv[2 * q + 1], hB = hv[2 * q + 1];
                    f0 = fma2(w0.x, hA.x, f0);
                    f1 = fma2(w0.y, hA.y, f1);
                    f2 = fma2(w1.x, hB.x, f2);
                    f3 = fma2(w1.y, hB.y, f3);
                }
                { ulonglong2 w0 = wv[28], hA = hv[28];
                  f0 = fma2(w0.x, hA.x, f0);
                  f1 = fma2(w0.y, hA.y, f1); }
                out_b[(size_t)(t - 1) * O_] =
                    pair_sum(add2(add2(f0, f1), add2(f2, f3))) + bfc;
            }

            // ---- h(t+1) = relu(W_ih x(t) + W_hh h(t) + bias), 8 accums
            u64 a0 = 0, a1 = 0, a2 = 0, a3 = 0, a4 = 0, a5 = 0, a6 = 0, a7 = 0;
            const float* xrow = x_buf[t & 3][r];
            const ulonglong2* xv = reinterpret_cast<const ulonglong2*>(xrow);
            #pragma unroll
            for (int q = 0; q < 6; q++) {
                ulonglong2 v0 = xv[2 * q], v1 = xv[2 * q + 1];
                a0 = fma2(wih[4 * q],     v0.x, a0);
                a1 = fma2(wih[4 * q + 1], v0.y, a1);
                a2 = fma2(wih[4 * q + 2], v1.x, a2);
                a3 = fma2(wih[4 * q + 3], v1.y, a3);
            }
            a4 = fma2(wih[24], reinterpret_cast<const u64*>(xrow)[24], a4);
            #pragma unroll
            for (int q = 0; q < 7; q++) {
                ulonglong2 v0 = hv[4 * q],     v1 = hv[4 * q + 1];
                ulonglong2 v2 = hv[4 * q + 2], v3 = hv[4 * q + 3];
                a0 = fma2(whh[8 * q],     v0.x, a0);
                a1 = fma2(whh[8 * q + 1], v0.y, a1);
                a2 = fma2(whh[8 * q + 2], v1.x, a2);
                a3 = fma2(whh[8 * q + 3], v1.y, a3);
                a4 = fma2(whh[8 * q + 4], v2.x, a4);
                a5 = fma2(whh[8 * q + 5], v2.y, a5);
                a6 = fma2(whh[8 * q + 6], v3.x, a6);
                a7 = fma2(whh[8 * q + 7], v3.y, a7);
            }
            { ulonglong2 v = hv[28];
              a6 = fma2(whh[56], v.x, a6);
              a7 = fma2(whh[57], v.y, a7); }
            float h = pair_sum(add2(add2(add2(a0, a1), add2(a2, a3)),
                                    add2(add2(a4, a5), add2(a6, a7)))) + bias;
            h = fmaxf(h, 0.f);
            h_buf[p ^ 1][r][j] = h;
        } else {
            // prefetch x for t+3 into slot (t+3)&3
            const int t3 = t + 3;
            if (t3 < T_) {
                cp8(&x_buf[t3 & 3][r][2 * u],        xb + t3 * I_ + 2 * u);
                cp8(&x_buf[t3 & 3][r][2 * (u + 12)], xb + t3 * I_ + 2 * (u + 12));
                if (u == 0) cp8(&x_buf[t3 & 3][r][48], xb + t3 * I_ + 48);
            }
            asm volatile("cp.async.commit_group;");
            asm volatile("cp.async.wait_group 2;");  // slot for t+1 complete
        }
        // per-row barrier: only this row's 4 warps participate
        asm volatile("bar.sync %0, 128;" :: "r"(bar_id) : "memory");
        p ^= 1;
    }

    // Epilogue: FC for the final timestep from h(T)
    if (is_fc) {
        const ulonglong2* hv =
            reinterpret_cast<const ulonglong2*>(h_buf[p][r]);
        const ulonglong2* wv =
            reinterpret_cast<const ulonglong2*>(wfc_s + lane * H_);
        u64 f0 = 0, f1 = 0, f2 = 0, f3 = 0;
        #pragma unroll
        for (int q = 0; q < 14; q++) {
            ulonglong2 w0 = wv[2 * q],     hA = hv[2 * q];
            ulonglong2 w1 = wv[2 * q + 1], hB = hv[2 * q + 1];
            f0 = fma2(w0.x, hA.x, f0);
            f1 = fma2(w0.y, hA.y, f1);
            f2 = fma2(w1.x, hB.x, f2);
            f3 = fma2(w1.y, hB.y, f3);
        }
        { ulonglong2 w0 = wv[28], hA = hv[28];
          f0 = fma2(w0.x, hA.x, f0);
          f1 = fma2(w0.y, hA.y, f1); }
        out_b[(size_t)(T_ - 1) * O_] =
            pair_sum(add2(add2(f0, f1), add2(f2, f3))) + bfc;
    }
}

// ---------------- launch ----------------
extern "C" void kernel_launch(void* const* d_in, const int* in_sizes, int n_in,
                              void* d_out, int out_size)
{
    const float* x    = (const float*)d_in[0];
    const float* W_ih = (const float*)d_in[1];
    const float* b_ih = (const float*)d_in[2];
    const float* W_hh = (const float*)d_in[3];
    const float* b_hh = (const float*)d_in[4];
    const float* W_fc = (const float*)d_in[5];
    const float* b_fc = (const float*)d_in[6];
    float* out = (float*)d_out;

    rnn_fused_kernel<<<B_ / 2, 256>>>(x, W_ih, b_ih, W_hh, b_hh,
                                      W_fc, b_fc, out);
}

// round 3
// speedup vs baseline: 1.8220x; 1.8220x over previous
#include <cuda_runtime.h>
#include <cstdint>

#define B_ 256
#define T_ 2048
#define I_ 50
#define H_ 116
#define O_ 50
#define N_TOT (B_ * T_)

typedef unsigned long long u64;

// Device scratch (static = allowed): xp = input projection, hs = hidden states
__device__ float g_xp[(size_t)N_TOT * H_];   // 243 MB
__device__ float g_hs[(size_t)N_TOT * H_];   // 243 MB

// ---------------- packed f32x2 helpers (Blackwell) ----------------
__device__ __forceinline__ u64 fma2(u64 a, u64 b, u64 c) {
    u64 d;
    asm("fma.rn.f32x2 %0, %1, %2, %3;" : "=l"(d) : "l"(a), "l"(b), "l"(c));
    return d;
}
__device__ __forceinline__ u64 add2(u64 a, u64 b) {
    u64 d;
    asm("add.rn.f32x2 %0, %1, %2;" : "=l"(d) : "l"(a), "l"(b));
    return d;
}
__device__ __forceinline__ float pair_sum(u64 a) {
    float lo = __uint_as_float((unsigned)(a & 0xFFFFFFFFull));
    float hi = __uint_as_float((unsigned)(a >> 32));
    return lo + hi;
}
__device__ __forceinline__ void cp16(void* smem, const void* gmem) {
    unsigned s = (unsigned)__cvta_generic_to_shared(smem);
    asm volatile("cp.async.ca.shared.global [%0], [%1], 16;" :: "r"(s), "l"(gmem));
}

// ================= small-N GEMM: out[n,j] = A[n,:]·W[j,:] + b1[j](+b2[j]) ==
// Register-tiled: each active thread computes RN rows x 4 cols.
// K even; KPAD multiple of 4 (>=K), rows zero-padded so no k-remainder.
template<int K, int KPAD, int J, int JG, int RN>
__global__ void gemm_small(const float* __restrict__ A,
                           const float* __restrict__ W,
                           const float* __restrict__ b1,
                           const float* __restrict__ b2,
                           float* __restrict__ out)
{
    constexpr int JP   = JG * 4;
    constexpr int ROWS = RN * 8;
    constexpr int KC2  = K / 2;
    constexpr int KP2  = KPAD / 2;
    __shared__ __align__(16) float a_s[ROWS * KPAD];
    __shared__ __align__(16) float w_s[JP * KPAD];
    __shared__ float b_s[JP];

    const int tid  = threadIdx.x;
    const int nthr = blockDim.x;

    // Stage W (zero-padded) + bias once per block
    {
        const u64* src = reinterpret_cast<const u64*>(W);
        u64* dst = reinterpret_cast<u64*>(w_s);
        for (int i = tid; i < JP * KP2; i += nthr) {
            int row = i / KP2, col = i % KP2;
            u64 v = 0;
            if (row < J && col < KC2) v = src[(size_t)row * KC2 + col];
            dst[i] = v;
        }
        for (int i = tid; i < JP; i += nthr)
            b_s[i] = (i < J) ? (b1[i] + (b2 ? b2[i] : 0.f)) : 0.f;
    }

    const int jg = tid % JG;
    const int ng = tid / JG;
    const bool active = (ng < 8);
    const int n0 = blockIdx.x * ROWS;

    __syncthreads();
    // Stage A tile (ROWS full rows are gmem-contiguous)
    {
        const u64* src = reinterpret_cast<const u64*>(A + (size_t)n0 * K);
        u64* dst = reinterpret_cast<u64*>(a_s);
        for (int i = tid; i < ROWS * KP2; i += nthr) {
            int col = i % KP2;
            int row = i / KP2;
            dst[i] = (col < KC2) ? src[(size_t)row * KC2 + col] : 0;
        }
    }
    __syncthreads();

    if (active) {
        const int j0 = jg * 4;
        const int r0 = ng * RN;
        u64 acc[RN][4];
        #pragma unroll
        for (int r = 0; r < RN; r++)
            #pragma unroll
            for (int m = 0; m < 4; m++) acc[r][m] = 0;

        #pragma unroll
        for (int k = 0; k < KPAD / 4; k++) {
            ulonglong2 wv[4];
            #pragma unroll
            for (int m = 0; m < 4; m++)
                wv[m] = reinterpret_cast<const ulonglong2*>(
                            w_s + (j0 + m) * KPAD)[k];
            #pragma unroll
            for (int r = 0; r < RN; r++) {
                ulonglong2 av = reinterpret_cast<const ulonglong2*>(
                                    a_s + (r0 + r) * KPAD)[k];
                #pragma unroll
                for (int m = 0; m < 4; m++) {
                    acc[r][m] = fma2(wv[m].x, av.x, acc[r][m]);
                    acc[r][m] = fma2(wv[m].y, av.y, acc[r][m]);
                }
            }
        }
        #pragma unroll
        for (int r = 0; r < RN; r++) {
            float* orow = out + (size_t)(n0 + r0 + r) * J;
            #pragma unroll
            for (int m = 0; m < 4; m++)
                if (j0 + m < J)
                    orow[j0 + m] = pair_sum(acc[r][m]) + b_s[j0 + m];
        }
    }
}

// ================= recurrence: h(t+1) = relu(xp(t) + W_hh·h(t)) ============
// 128 CTAs x 256 threads; CTA = 2 batch rows; per 128-thread half:
//   lanes [0,115]  : compute h[j], W_hh row register-resident
//   lanes [116,127]: prefetch xp rows via cp.async (3-step lead, 4-slot ring)
__global__ void __launch_bounds__(256, 1) rnn_kernel(
    const float* __restrict__ W_hh)
{
    __shared__ __align__(16) float h_buf[2][2][120];   // [pingpong][row][j]
    __shared__ __align__(16) float x_buf[4][2][120];   // xp ring, 116 used

    const int tid  = threadIdx.x;
    const int r    = tid >> 7;
    const int lane = tid & 127;
    const int b    = blockIdx.x * 2 + r;
    const bool is_j = (lane < H_);
    const int j = lane;

    u64 whh[58];
    if (is_j) {
        const u64* p2 = reinterpret_cast<const u64*>(W_hh + j * H_);
        #pragma unroll
        for (int q = 0; q < 58; q++) whh[q] = p2[q];
        h_buf[0][r][j] = 0.f;
    }

    const float* xpb = g_xp + (size_t)b * T_ * H_;   // rows are 464B = 29x16B
    const int u = lane - H_;                          // loader index 0..11

    if (!is_j) {
        #pragma unroll
        for (int s = 0; s < 3; s++) {
            const float* row = xpb + (size_t)s * H_;
            cp16(&x_buf[s][r][4 * u],        row + 4 * u);
            cp16(&x_buf[s][r][4 * (u + 12)], row + 4 * (u + 12));
            if (u < 5) cp16(&x_buf[s][r][4 * (u + 24)], row + 4 * (u + 24));
            asm volatile("cp.async.commit_group;");
        }
        asm volatile("cp.async.wait_group 2;");   // slot 0 complete
    }
    __syncthreads();

    float* hs_ptr = g_hs + (size_t)b * T_ * H_ + j;
    const int bar_id = r + 1;
    int p = 0;
    for (int t = 0; t < T_; t++) {
        if (is_j) {
            const ulonglong2* hv =
                reinterpret_cast<const ulonglong2*>(h_buf[p][r]);
            // a0 starts as (xp, 0) packed -> bias+input folded in for free
            u64 a0 = (u64)__float_as_uint(x_buf[t & 3][r][j]);
            u64 a1 = 0, a2 = 0, a3 = 0, a4 = 0, a5 = 0, a6 = 0, a7 = 0;
            #pragma unroll
            for (int q = 0; q < 7; q++) {
                ulonglong2 v0 = hv[4 * q],     v1 = hv[4 * q + 1];
                ulonglong2 v2 = hv[4 * q + 2], v3 = hv[4 * q + 3];
                a0 = fma2(whh[8 * q],     v0.x, a0);
                a1 = fma2(whh[8 * q + 1], v0.y, a1);
                a2 = fma2(whh[8 * q + 2], v1.x, a2);
                a3 = fma2(whh[8 * q + 3], v1.y, a3);
                a4 = fma2(whh[8 * q + 4], v2.x, a4);
                a5 = fma2(whh[8 * q + 5], v2.y, a5);
                a6 = fma2(whh[8 * q + 6], v3.x, a6);
                a7 = fma2(whh[8 * q + 7], v3.y, a7);
            }
            { ulonglong2 v = hv[28];
              a6 = fma2(whh[56], v.x, a6);
              a7 = fma2(whh[57], v.y, a7); }
            float h = pair_sum(add2(add2(add2(a0, a1), add2(a2, a3)),
                                    add2(add2(a4, a5), add2(a6, a7))));
            h = fmaxf(h, 0.f);
            h_buf[p ^ 1][r][j] = h;
            hs_ptr[0] = h;                       // coalesced row for FC kernel
            hs_ptr += H_;
        } else {
            const int t3 = t + 3;
            if (t3 < T_) {
                const float* row = xpb + (size_t)t3 * H_;
                cp16(&x_buf[t3 & 3][r][4 * u],        row + 4 * u);
                cp16(&x_buf[t3 & 3][r][4 * (u + 12)], row + 4 * (u + 12));
                if (u < 5)
                    cp16(&x_buf[t3 & 3][r][4 * (u + 24)], row + 4 * (u + 24));
            }
            asm volatile("cp.async.commit_group;");
            asm volatile("cp.async.wait_group 2;");  // slot t+1 complete
        }
        asm volatile("bar.sync %0, 128;" :: "r"(bar_id) : "memory");
        p ^= 1;
    }
}

// ---------------- launch ----------------
extern "C" void kernel_launch(void* const* d_in, const int* in_sizes, int n_in,
                              void* d_out, int out_size)
{
    const float* x    = (const float*)d_in[0];
    const float* W_ih = (const float*)d_in[1];
    const float* b_ih = (const float*)d_in[2];
    const float* W_hh = (const float*)d_in[3];
    const float* b_hh = (const float*)d_in[4];
    const float* W_fc = (const float*)d_in[5];
    const float* b_fc = (const float*)d_in[6];
    float* out = (float*)d_out;

    float* xp; cudaGetSymbolAddress((void**)&xp, g_xp);
    float* hs; cudaGetSymbolAddress((void**)&hs, g_hs);

    // xp = x·W_ihT + (b_ih + b_hh):  K=50 (pad 52), J=116, 32 rows/block
    gemm_small<50, 52, 116, 29, 4>
        <<<N_TOT / 32, 256>>>(x, W_ih, b_ih, b_hh, xp);
    // serial ReLU recurrence
    rnn_kernel<<<B_ / 2, 256>>>(W_hh);
    // out = hs·W_fcT + b_fc:  K=116, J=50 (JG=13), 32 rows/block
    gemm_small<116, 116, 50, 13, 4>
        <<<N_TOT / 32, 128>>>(hs, W_fc, b_fc, nullptr, out);
}

// round 4
// speedup vs baseline: 2.3168x; 1.2715x over previous
#include <cuda_runtime.h>
#include <cstdint>

#define B_ 256
#define T_ 2048
#define I_ 50
#define H_ 116
#define O_ 50
#define N_TOT (B_ * T_)

typedef unsigned long long u64;

// Device scratch (static allocation = allowed)
__device__ float g_xp[(size_t)N_TOT * H_];   // input projection [N, H]
__device__ float g_hs[(size_t)N_TOT * H_];   // hidden states    [N, H]

// ---------------- packed f32x2 helpers (Blackwell) ----------------
__device__ __forceinline__ u64 fma2(u64 a, u64 b, u64 c) {
    u64 d;
    asm("fma.rn.f32x2 %0, %1, %2, %3;" : "=l"(d) : "l"(a), "l"(b), "l"(c));
    return d;
}
__device__ __forceinline__ u64 add2(u64 a, u64 b) {
    u64 d;
    asm("add.rn.f32x2 %0, %1, %2;" : "=l"(d) : "l"(a), "l"(b));
    return d;
}
__device__ __forceinline__ float pair_sum(u64 a) {
    float lo = __uint_as_float((unsigned)(a & 0xFFFFFFFFull));
    float hi = __uint_as_float((unsigned)(a >> 32));
    return lo + hi;
}
__device__ __forceinline__ void cp16(void* smem, const void* gmem) {
    unsigned s = (unsigned)__cvta_generic_to_shared(smem);
    asm volatile("cp.async.ca.shared.global [%0], [%1], 16;" :: "r"(s), "l"(gmem));
}
#define CP_COMMIT() asm volatile("cp.async.commit_group;")
#define CP_WAIT(n)  asm volatile("cp.async.wait_group %0;" :: "n"(n))

// ================= xp GEMM: g_xp[n,j] = x[n,:]·W_ih[j,:] + b_ih[j]+b_hh[j] ==
// Thread j holds W_ih row j in registers; x rows broadcast from shared.
#define XP_ROWS 32
#define XP_NT   (N_TOT / XP_ROWS)          // 16384 tiles
__global__ void __launch_bounds__(256) xp_kernel(
    const float* __restrict__ x,
    const float* __restrict__ W_ih,
    const float* __restrict__ b_ih,
    const float* __restrict__ b_hh)
{
    __shared__ __align__(16) float xs[2][XP_ROWS * I_];   // 2 x 6400B

    const int tid = threadIdx.x;
    const int j   = tid & 127;        // output column
    const int r2  = tid >> 7;         // row-of-pair
    const bool is_j = (j < H_);

    u64 wih[25];
    float bias = 0.f;
    if (is_j) {
        const u64* p = reinterpret_cast<const u64*>(W_ih + j * I_);  // 200B*j, 8-aligned
        #pragma unroll
        for (int q = 0; q < 25; q++) wih[q] = p[q];
        bias = b_ih[j] + b_hh[j];
    }

    int tile = blockIdx.x;
    // prologue: stage first tile
    if (tile < XP_NT) {
        const float* src = x + (size_t)tile * (XP_ROWS * I_);
        for (int i = tid; i < (XP_ROWS * I_) / 4; i += 256)
            cp16(&xs[0][4 * i], src + 4 * i);
    }
    CP_COMMIT();

    int pb = 0;
    for (; tile < XP_NT; tile += gridDim.x) {
        const int nxt = tile + gridDim.x;
        if (nxt < XP_NT) {
            const float* src = x + (size_t)nxt * (XP_ROWS * I_);
            for (int i = tid; i < (XP_ROWS * I_) / 4; i += 256)
                cp16(&xs[pb ^ 1][4 * i], src + 4 * i);
        }
        CP_COMMIT();
        CP_WAIT(1);          // current tile arrived
        __syncthreads();

        if (is_j) {
            float* orow = g_xp + (size_t)tile * XP_ROWS * H_ + j;
            #pragma unroll 2
            for (int i = 0; i < XP_ROWS / 2; i++) {
                const int row = 2 * i + r2;
                const u64* av = reinterpret_cast<const u64*>(xs[pb] + row * I_);
                u64 a0 = 0, a1 = 0, a2 = 0, a3 = 0;
                #pragma unroll
                for (int q = 0; q < 6; q++) {
                    a0 = fma2(wih[4 * q],     av[4 * q],     a0);
                    a1 = fma2(wih[4 * q + 1], av[4 * q + 1], a1);
                    a2 = fma2(wih[4 * q + 2], av[4 * q + 2], a2);
                    a3 = fma2(wih[4 * q + 3], av[4 * q + 3], a3);
                }
                a0 = fma2(wih[24], av[24], a0);
                orow[(size_t)row * H_] =
                    pair_sum(add2(add2(a0, a1), add2(a2, a3))) + bias;
            }
        }
        __syncthreads();     // compute done before this buffer is overwritten
        pb ^= 1;
    }
}

// ================= FC GEMM: out[n,o] = hs[n,:]·W_fc[o,:] + b_fc[o] =========
// Thread o holds W_fc row o in registers; hs rows broadcast from shared.
#define FC_ROWS 16
#define FC_NT   (N_TOT / FC_ROWS)          // 32768 tiles
__global__ void __launch_bounds__(256) fc_kernel(
    const float* __restrict__ W_fc,
    const float* __restrict__ b_fc,
    float* __restrict__ out)
{
    __shared__ __align__(16) float hs_s[2][FC_ROWS * H_];   // 2 x 7424B

    const int tid = threadIdx.x;
    const int o   = tid & 63;
    const int g   = tid >> 6;         // row group 0..3
    const bool is_o = (o < O_);

    u64 wfc[58];
    float bias = 0.f;
    if (is_o) {
        const u64* p = reinterpret_cast<const u64*>(W_fc + o * H_);  // 464B*o
        #pragma unroll
        for (int q = 0; q < 58; q++) wfc[q] = p[q];
        bias = b_fc[o];
    }

    const float* hs = g_hs;
    int tile = blockIdx.x;
    if (tile < FC_NT) {
        const float* src = hs + (size_t)tile * (FC_ROWS * H_);
        for (int i = tid; i < (FC_ROWS * H_) / 4; i += 256)
            cp16(&hs_s[0][4 * i], src + 4 * i);
    }
    CP_COMMIT();

    int pb = 0;
    for (; tile < FC_NT; tile += gridDim.x) {
        const int nxt = tile + gridDim.x;
        if (nxt < FC_NT) {
            const float* src = hs + (size_t)nxt * (FC_ROWS * H_);
            for (int i = tid; i < (FC_ROWS * H_) / 4; i += 256)
                cp16(&hs_s[pb ^ 1][4 * i], src + 4 * i);
        }
        CP_COMMIT();
        CP_WAIT(1);
        __syncthreads();

        if (is_o) {
            #pragma unroll
            for (int i = 0; i < FC_ROWS / 4; i++) {
                const int row = 4 * i + g;
                const ulonglong2* av = reinterpret_cast<const ulonglong2*>(
                    hs_s[pb] + row * H_);              // 464B stride, 16-aligned
                u64 a0 = 0, a1 = 0, a2 = 0, a3 = 0,
                    a4 = 0, a5 = 0, a6 = 0, a7 = 0;
                #pragma unroll
                for (int q = 0; q < 7; q++) {
                    ulonglong2 v0 = av[4 * q],     v1 = av[4 * q + 1];
                    ulonglong2 v2 = av[4 * q + 2], v3 = av[4 * q + 3];
                    a0 = fma2(wfc[8 * q],     v0.x, a0);
                    a1 = fma2(wfc[8 * q + 1], v0.y, a1);
                    a2 = fma2(wfc[8 * q + 2], v1.x, a2);
                    a3 = fma2(wfc[8 * q + 3], v1.y, a3);
                    a4 = fma2(wfc[8 * q + 4], v2.x, a4);
                    a5 = fma2(wfc[8 * q + 5], v2.y, a5);
                    a6 = fma2(wfc[8 * q + 6], v3.x, a6);
                    a7 = fma2(wfc[8 * q + 7], v3.y, a7);
                }
                { ulonglong2 v = av[28];
                  a6 = fma2(wfc[56], v.x, a6);
                  a7 = fma2(wfc[57], v.y, a7); }
                out[(size_t)(tile * FC_ROWS + row) * O_ + o] =
                    pair_sum(add2(add2(add2(a0, a1), add2(a2, a3)),
                                  add2(add2(a4, a5), add2(a6, a7)))) + bias;
            }
        }
        __syncthreads();
        pb ^= 1;
    }
}

// ================= recurrence: h(t+1) = relu(xp(t) + W_hh·h(t)) ============
// 128 CTAs x 512 threads; CTA = 2 batch rows. Per row (256 threads):
//   half p in {0,1} handles k-range [58p, 58p+58): 29 fma2/thread/step
//   p1 lanes j>=116: cp.async prefetch of xp rows (3-step lead, 4-slot ring)
// Two named barriers per step: (partials ready) and (h ready).
__global__ void __launch_bounds__(512, 1) rnn_kernel(
    const float* __restrict__ W_hh)
{
    __shared__ __align__(16) float h_s[2][128];     // [row][j] single buffer
    __shared__ float part1[2][128];                  // p1 partials
    __shared__ __align__(16) float x_s[4][2][120];   // xp ring per row

    const int tid = threadIdx.x;
    const int r   = tid >> 8;          // batch row within CTA
    const int sub = tid & 255;
    const int p   = sub >> 7;          // k-half
    const int j   = sub & 127;
    const int b   = blockIdx.x * 2 + r;
    const bool is_j = (j < H_);

    u64 whh[29];
    if (is_j) {
        // W_hh row j, k-half p: byte offset 464*j + 232*p (8-aligned)
        const u64* pw = reinterpret_cast<const u64*>(W_hh + j * H_ + p * 58);
        #pragma unroll
        for (int q = 0; q < 29; q++) whh[q] = pw[q];
        if (p == 0) h_s[r][j] = 0.f;
    }

    const float* xpb = g_xp + (size_t)b * T_ * H_;   // rows 464B, 16-aligned
    const int u = j - H_;                             // loader index 0..11
    const bool is_ld = (p == 1) && !is_j;

    if (is_ld) {
        #pragma unroll
        for (int s = 0; s < 3; s++) {
            const float* row = xpb + (size_t)s * H_;
            cp16(&x_s[s][r][4 * u],        row + 4 * u);
            cp16(&x_s[s][r][4 * (u + 12)], row + 4 * (u + 12));
            if (u < 5) cp16(&x_s[s][r][4 * (u + 24)], row + 4 * (u + 24));
            CP_COMMIT();
        }
        CP_WAIT(2);    // slot 0 complete
    }
    __syncthreads();

    float* hs_ptr = g_hs + (size_t)b * T_ * H_ + j;
    const int bar_id = r + 1;
    for (int t = 0; t < T_; t++) {
        float partial = 0.f;
        if (is_j) {
            const u64* hv = reinterpret_cast<const u64*>(h_s[r]) + 29 * p;
            u64 a0 = (p == 0) ? (u64)__float_as_uint(x_s[t & 3][r][j]) : 0;
            u64 a1 = 0, a2 = 0, a3 = 0;
            #pragma unroll
            for (int q = 0; q < 7; q++) {
                a0 = fma2(whh[4 * q],     hv[4 * q],     a0);
                a1 = fma2(whh[4 * q + 1], hv[4 * q + 1], a1);
                a2 = fma2(whh[4 * q + 2], hv[4 * q + 2], a2);
                a3 = fma2(whh[4 * q + 3], hv[4 * q + 3], a3);
            }
            a0 = fma2(whh[28], hv[28], a0);
            partial = pair_sum(add2(add2(a0, a1), add2(a2, a3)));
            if (p == 1) part1[r][j] = partial;
        } else if (is_ld) {
            const int t3 = t + 3;
            if (t3 < T_) {
                const float* row = xpb + (size_t)t3 * H_;
                cp16(&x_s[t3 & 3][r][4 * u],        row + 4 * u);
                cp16(&x_s[t3 & 3][r][4 * (u + 12)], row + 4 * (u + 12));
                if (u < 5)
                    cp16(&x_s[t3 & 3][r][4 * (u + 24)], row + 4 * (u + 24));
            }
            CP_COMMIT();
            CP_WAIT(2);    // slot t+1 complete
        }
        asm volatile("bar.sync %0, 256;" :: "r"(bar_id) : "memory");
        if (p == 0 && is_j) {
            float h = fmaxf(partial + part1[r][j], 0.f);
            h_s[r][j] = h;
            hs_ptr[0] = h;
            hs_ptr += H_;
        }
        asm volatile("bar.sync %0, 256;" :: "r"(bar_id) : "memory");
    }
}

// ---------------- launch ----------------
extern "C" void kernel_launch(void* const* d_in, const int* in_sizes, int n_in,
                              void* d_out, int out_size)
{
    const float* x    = (const float*)d_in[0];
    const float* W_ih = (const float*)d_in[1];
    const float* b_ih = (const float*)d_in[2];
    const float* W_hh = (const float*)d_in[3];
    const float* b_hh = (const float*)d_in[4];
    const float* W_fc = (const float*)d_in[5];
    const float* b_fc = (const float*)d_in[6];
    float* out = (float*)d_out;

    xp_kernel<<<4096, 256>>>(x, W_ih, b_ih, b_hh);
    rnn_kernel<<<B_ / 2, 512>>>(W_hh);
    fc_kernel<<<2048, 256>>>(W_fc, b_fc, out);
}

// round 5
// speedup vs baseline: 2.3280x; 1.0048x over previous
#include <cuda_runtime.h>
#include <cstdint>

#define B_ 256
#define T_ 2048
#define I_ 50
#define H_ 116
#define O_ 50
#define N_TOT (B_ * T_)

typedef unsigned long long u64;

// Device scratch (static allocation = allowed)
__device__ float g_xp[(size_t)N_TOT * H_];   // input projection [N, H]
__device__ float g_hs[(size_t)N_TOT * H_];   // hidden states    [N, H]

// ---------------- packed f32x2 helpers (Blackwell) ----------------
__device__ __forceinline__ u64 fma2(u64 a, u64 b, u64 c) {
    u64 d;
    asm("fma.rn.f32x2 %0, %1, %2, %3;" : "=l"(d) : "l"(a), "l"(b), "l"(c));
    return d;
}
__device__ __forceinline__ u64 add2(u64 a, u64 b) {
    u64 d;
    asm("add.rn.f32x2 %0, %1, %2;" : "=l"(d) : "l"(a), "l"(b));
    return d;
}
__device__ __forceinline__ float pair_sum(u64 a) {
    float lo = __uint_as_float((unsigned)(a & 0xFFFFFFFFull));
    float hi = __uint_as_float((unsigned)(a >> 32));
    return lo + hi;
}
__device__ __forceinline__ void cp16(void* smem, const void* gmem) {
    unsigned s = (unsigned)__cvta_generic_to_shared(smem);
    asm volatile("cp.async.ca.shared.global [%0], [%1], 16;" :: "r"(s), "l"(gmem));
}
__device__ __forceinline__ void cp8(void* smem, const void* gmem) {
    unsigned s = (unsigned)__cvta_generic_to_shared(smem);
    asm volatile("cp.async.ca.shared.global [%0], [%1], 8;" :: "r"(s), "l"(gmem));
}
#define CP_COMMIT() asm volatile("cp.async.commit_group;")
#define CP_WAIT(n)  asm volatile("cp.async.wait_group %0;" :: "n"(n))

// ================= xp GEMM: g_xp[n,j] = x[n,:]·W_ih[j,:] + b_ih[j]+b_hh[j] ==
// Thread j holds W_ih row j in registers; x rows broadcast from shared.
// Smem rows padded to 52 floats (208B, 16-aligned) -> LDS.128 reads.
#define XP_ROWS 32
#define XP_RPAD 52
#define XP_NT   (N_TOT / XP_ROWS)          // 16384 tiles
__global__ void __launch_bounds__(256) xp_kernel(
    const float* __restrict__ x,
    const float* __restrict__ W_ih,
    const float* __restrict__ b_ih,
    const float* __restrict__ b_hh)
{
    __shared__ __align__(16) float xs[2][XP_ROWS * XP_RPAD];

    const int tid = threadIdx.x;
    const int j   = tid & 127;        // output column
    const int r2  = tid >> 7;         // row-of-pair
    const bool is_j = (j < H_);

    u64 wih[25];
    float bias = 0.f;
    if (is_j) {
        const u64* p = reinterpret_cast<const u64*>(W_ih + j * I_);
        #pragma unroll
        for (int q = 0; q < 25; q++) wih[q] = p[q];
        bias = b_ih[j] + b_hh[j];
    }

    // stage helper: 25 cp8 per row into padded layout
    auto stage = [&](int tile, int buf) {
        const float* src = x + (size_t)tile * (XP_ROWS * I_);
        for (int i = tid; i < XP_ROWS * 25; i += 256) {
            int row = i / 25, c = i - 25 * row;
            cp8(&xs[buf][row * XP_RPAD + 2 * c], src + row * I_ + 2 * c);
        }
    };

    int tile = blockIdx.x;
    if (tile < XP_NT) stage(tile, 0);
    CP_COMMIT();

    int pb = 0;
    for (; tile < XP_NT; tile += gridDim.x) {
        const int nxt = tile + gridDim.x;
        if (nxt < XP_NT) stage(nxt, pb ^ 1);
        CP_COMMIT();
        CP_WAIT(1);          // current tile arrived
        __syncthreads();

        if (is_j) {
            float* orow = g_xp + (size_t)tile * XP_ROWS * H_ + j;
            #pragma unroll 2
            for (int i = 0; i < XP_ROWS / 2; i++) {
                const int row = 2 * i + r2;
                const float* rbase = xs[pb] + row * XP_RPAD;
                const ulonglong2* av =
                    reinterpret_cast<const ulonglong2*>(rbase);
                u64 a0 = 0, a1 = 0, a2 = 0, a3 = 0;
                #pragma unroll
                for (int q = 0; q < 12; q++) {
                    ulonglong2 v = av[q];
                    if (q & 1) {
                        a2 = fma2(wih[2 * q],     v.x, a2);
                        a3 = fma2(wih[2 * q + 1], v.y, a3);
                    } else {
                        a0 = fma2(wih[2 * q],     v.x, a0);
                        a1 = fma2(wih[2 * q + 1], v.y, a1);
                    }
                }
                a0 = fma2(wih[24],
                          reinterpret_cast<const u64*>(rbase)[24], a0);
                orow[(size_t)row * H_] =
                    pair_sum(add2(add2(a0, a1), add2(a2, a3))) + bias;
            }
        }
        __syncthreads();     // compute done before buffer overwrite
        pb ^= 1;
    }
}

// ================= FC GEMM: out[n,o] = hs[n,:]·W_fc[o,:] + b_fc[o] =========
#define FC_ROWS 16
#define FC_NT   (N_TOT / FC_ROWS)
__global__ void __launch_bounds__(256) fc_kernel(
    const float* __restrict__ W_fc,
    const float* __restrict__ b_fc,
    float* __restrict__ out)
{
    __shared__ __align__(16) float hs_s[2][FC_ROWS * H_];

    const int tid = threadIdx.x;
    const int o   = tid & 63;
    const int g   = tid >> 6;
    const bool is_o = (o < O_);

    u64 wfc[58];
    float bias = 0.f;
    if (is_o) {
        const u64* p = reinterpret_cast<const u64*>(W_fc + o * H_);
        #pragma unroll
        for (int q = 0; q < 58; q++) wfc[q] = p[q];
        bias = b_fc[o];
    }

    const float* hs = g_hs;
    int tile = blockIdx.x;
    if (tile < FC_NT) {
        const float* src = hs + (size_t)tile * (FC_ROWS * H_);
        for (int i = tid; i < (FC_ROWS * H_) / 4; i += 256)
            cp16(&hs_s[0][4 * i], src + 4 * i);
    }
    CP_COMMIT();

    int pb = 0;
    for (; tile < FC_NT; tile += gridDim.x) {
        const int nxt = tile + gridDim.x;
        if (nxt < FC_NT) {
            const float* src = hs + (size_t)nxt * (FC_ROWS * H_);
            for (int i = tid; i < (FC_ROWS * H_) / 4; i += 256)
                cp16(&hs_s[pb ^ 1][4 * i], src + 4 * i);
        }
        CP_COMMIT();
        CP_WAIT(1);
        __syncthreads();

        if (is_o) {
            #pragma unroll
            for (int i = 0; i < FC_ROWS / 4; i++) {
                const int row = 4 * i + g;
                const ulonglong2* av = reinterpret_cast<const ulonglong2*>(
                    hs_s[pb] + row * H_);
                u64 a0 = 0, a1 = 0, a2 = 0, a3 = 0,
                    a4 = 0, a5 = 0, a6 = 0, a7 = 0;
                #pragma unroll
                for (int q = 0; q < 7; q++) {
                    ulonglong2 v0 = av[4 * q],     v1 = av[4 * q + 1];
                    ulonglong2 v2 = av[4 * q + 2], v3 = av[4 * q + 3];
                    a0 = fma2(wfc[8 * q],     v0.x, a0);
                    a1 = fma2(wfc[8 * q + 1], v0.y, a1);
                    a2 = fma2(wfc[8 * q + 2], v1.x, a2);
                    a3 = fma2(wfc[8 * q + 3], v1.y, a3);
                    a4 = fma2(wfc[8 * q + 4], v2.x, a4);
                    a5 = fma2(wfc[8 * q + 5], v2.y, a5);
                    a6 = fma2(wfc[8 * q + 6], v3.x, a6);
                    a7 = fma2(wfc[8 * q + 7], v3.y, a7);
                }
                { ulonglong2 v = av[28];
                  a6 = fma2(wfc[56], v.x, a6);
                  a7 = fma2(wfc[57], v.y, a7); }
                out[(size_t)(tile * FC_ROWS + row) * O_ + o] =
                    pair_sum(add2(add2(add2(a0, a1), add2(a2, a3)),
                                  add2(add2(a4, a5), add2(a6, a7)))) + bias;
            }
        }
        __syncthreads();
        pb ^= 1;
    }
}

// ================= recurrence: h(t+1) = relu(xp(t) + W_hh·h(t)) ============
// 128 CTAs x 512 threads; CTA = 2 batch rows (r = tid>>8).
// Lane pair (2j, 2j+1) computes h[j]: half0 takes k[0,60), half1 k[60,116)
// (both 16B-aligned -> pure LDS.128). Partials merged via shfl.bfly(1).
// ONE named barrier per step (h ping-pong). h tail [116,128) stays zero so
// the uniform 15x LDS.128 loop reads zeros x zero-weights for half1's tail.
// Lanes s in [232,256): cp.async prefetch of xp rows (3-step lead, ring of 4).
__global__ void __launch_bounds__(512, 1) rnn_kernel(
    const float* __restrict__ W_hh)
{
    __shared__ __align__(16) float h_s[2][2][128];   // [pingpong][row][j]
    __shared__ __align__(16) float x_s[4][2][120];   // xp ring per row

    const int tid  = threadIdx.x;
    const int r    = tid >> 8;
    const int s    = tid & 255;
    const int j    = s >> 1;           // 0..127
    const int half = s & 1;
    const int b    = blockIdx.x * 2 + r;
    const bool comp   = (j < H_);
    const bool loader = (s >= 232);    // 24 lanes per row

    // zero both h ping-pong buffers (incl. tail 116..127)
    if (half == 0) { h_s[0][r][j] = 0.f; h_s[1][r][j] = 0.f; }

    u64 w[30];
    if (comp) {
        const u64* wsrc =
            reinterpret_cast<const u64*>(W_hh + j * H_ + 60 * half);
        const int nw = 30 - 2 * half;   // half0: 30, half1: 28
        #pragma unroll
        for (int q = 0; q < 30; q++) w[q] = (q < nw) ? wsrc[q] : 0ull;
    }

    const float* xpb = g_xp + (size_t)b * T_ * H_;   // rows 464B, 16-aligned
    const int u = s - 232;                            // loader index 0..23

    if (loader) {
        #pragma unroll
        for (int t0 = 0; t0 < 3; t0++) {
            const float* row = xpb + (size_t)t0 * H_;
            cp16(&x_s[t0][r][4 * u], row + 4 * u);
            if (u < 5) cp16(&x_s[t0][r][4 * (u + 24)], row + 4 * (u + 24));
            CP_COMMIT();
        }
        CP_WAIT(2);    // slot 0 complete
    }
    __syncthreads();

    float* hs_ptr = g_hs + (size_t)b * T_ * H_ + j;
    const int bar_id = r + 1;
    int p = 0;
    for (int t = 0; t < T_; t++) {
        float partial = 0.f;
        if (comp) {
            const ulonglong2* hv =
                reinterpret_cast<const ulonglong2*>(h_s[p][r]) + 15 * half;
            // fold xp into half0's first accumulator: a0 = (xp, 0)
            u64 a0 = half ? 0ull
                          : (u64)__float_as_uint(x_s[t & 3][r][j]);
            u64 a1 = 0, a2 = 0, a3 = 0;
            #pragma unroll
            for (int q = 0; q < 15; q++) {
                ulonglong2 v = hv[q];
                if (q & 1) {
                    a2 = fma2(w[2 * q],     v.x, a2);
                    a3 = fma2(w[2 * q + 1], v.y, a3);
                } else {
                    a0 = fma2(w[2 * q],     v.x, a0);
                    a1 = fma2(w[2 * q + 1], v.y, a1);
                }
            }
            partial = pair_sum(add2(add2(a0, a1), add2(a2, a3)));
        } else if (loader) {
            const int t3 = t + 3;
            if (t3 < T_) {
                const float* row = xpb + (size_t)t3 * H_;
                cp16(&x_s[t3 & 3][r][4 * u], row + 4 * u);
                if (u < 5)
                    cp16(&x_s[t3 & 3][r][4 * (u + 24)], row + 4 * (u + 24));
            }
            CP_COMMIT();
            CP_WAIT(2);    // slot t+1 complete
        }
        // fully-converged warp shuffle: pair-exchange partials
        float other = __shfl_xor_sync(0xFFFFFFFFu, partial, 1);
        if (comp & (half == 0)) {
            float h = fmaxf(partial + other, 0.f);
            h_s[p ^ 1][r][j] = h;
            hs_ptr[0] = h;
            hs_ptr += H_;
        }
        asm volatile("bar.sync %0, 256;" :: "r"(bar_id) : "memory");
        p ^= 1;
    }
}

// ---------------- launch ----------------
extern "C" void kernel_launch(void* const* d_in, const int* in_sizes, int n_in,
                              void* d_out, int out_size)
{
    const float* x    = (const float*)d_in[0];
    const float* W_ih = (const float*)d_in[1];
    const float* b_ih = (const float*)d_in[2];
    const float* W_hh = (const float*)d_in[3];
    const float* b_hh = (const float*)d_in[4];
    const float* W_fc = (const float*)d_in[5];
    const float* b_fc = (const float*)d_in[6];
    float* out = (float*)d_out;

    xp_kernel<<<4096, 256>>>(x, W_ih, b_ih, b_hh);
    rnn_kernel<<<B_ / 2, 512>>>(W_hh);
    fc_kernel<<<2048, 256>>>(W_fc, b_fc, out);
}

// round 6
// speedup vs baseline: 2.4731x; 1.0624x over previous
#include <cuda_runtime.h>
#include <cstdint>

#define B_ 256
#define T_ 2048
#define I_ 50
#define H_ 116
#define O_ 50
#define N_TOT (B_ * T_)

typedef unsigned long long u64;

// Device scratch (static allocation = allowed)
__device__ float g_xp[(size_t)N_TOT * H_];   // input projection [N, H]
__device__ float g_hs[(size_t)N_TOT * H_];   // hidden states    [N, H]

// ---------------- packed f32x2 helpers (Blackwell) ----------------
__device__ __forceinline__ u64 fma2(u64 a, u64 b, u64 c) {
    u64 d;
    asm("fma.rn.f32x2 %0, %1, %2, %3;" : "=l"(d) : "l"(a), "l"(b), "l"(c));
    return d;
}
__device__ __forceinline__ u64 add2(u64 a, u64 b) {
    u64 d;
    asm("add.rn.f32x2 %0, %1, %2;" : "=l"(d) : "l"(a), "l"(b));
    return d;
}
__device__ __forceinline__ float pair_sum(u64 a) {
    float lo = __uint_as_float((unsigned)(a & 0xFFFFFFFFull));
    float hi = __uint_as_float((unsigned)(a >> 32));
    return lo + hi;
}
__device__ __forceinline__ void cp16(void* smem, const void* gmem) {
    unsigned s = (unsigned)__cvta_generic_to_shared(smem);
    asm volatile("cp.async.ca.shared.global [%0], [%1], 16;" :: "r"(s), "l"(gmem));
}
__device__ __forceinline__ void cp8(void* smem, const void* gmem) {
    unsigned s = (unsigned)__cvta_generic_to_shared(smem);
    asm volatile("cp.async.ca.shared.global [%0], [%1], 8;" :: "r"(s), "l"(gmem));
}
#define CP_COMMIT() asm volatile("cp.async.commit_group;")
#define CP_WAIT(n)  asm volatile("cp.async.wait_group %0;" :: "n"(n))

// ================= xp GEMM: g_xp[n,j] = x[n,:]·W_ih[j,:] + b_ih[j]+b_hh[j] ==
#define XP_ROWS 32
#define XP_RPAD 52
#define XP_NT   (N_TOT / XP_ROWS)
__global__ void __launch_bounds__(256) xp_kernel(
    const float* __restrict__ x,
    const float* __restrict__ W_ih,
    const float* __restrict__ b_ih,
    const float* __restrict__ b_hh)
{
    __shared__ __align__(16) float xs[2][XP_ROWS * XP_RPAD];

    const int tid = threadIdx.x;
    const int j   = tid & 127;
    const int r2  = tid >> 7;
    const bool is_j = (j < H_);

    u64 wih[25];
    float bias = 0.f;
    if (is_j) {
        const u64* p = reinterpret_cast<const u64*>(W_ih + j * I_);
        #pragma unroll
        for (int q = 0; q < 25; q++) wih[q] = p[q];
        bias = b_ih[j] + b_hh[j];
    }

    auto stage = [&](int tile, int buf) {
        const float* src = x + (size_t)tile * (XP_ROWS * I_);
        for (int i = tid; i < XP_ROWS * 25; i += 256) {
            int row = i / 25, c = i - 25 * row;
            cp8(&xs[buf][row * XP_RPAD + 2 * c], src + row * I_ + 2 * c);
        }
    };

    int tile = blockIdx.x;
    if (tile < XP_NT) stage(tile, 0);
    CP_COMMIT();

    int pb = 0;
    for (; tile < XP_NT; tile += gridDim.x) {
        const int nxt = tile + gridDim.x;
        if (nxt < XP_NT) stage(nxt, pb ^ 1);
        CP_COMMIT();
        CP_WAIT(1);
        __syncthreads();

        if (is_j) {
            float* orow = g_xp + (size_t)tile * XP_ROWS * H_ + j;
            #pragma unroll 2
            for (int i = 0; i < XP_ROWS / 2; i++) {
                const int row = 2 * i + r2;
                const float* rbase = xs[pb] + row * XP_RPAD;
                const ulonglong2* av =
                    reinterpret_cast<const ulonglong2*>(rbase);
                u64 a0 = 0, a1 = 0, a2 = 0, a3 = 0;
                #pragma unroll
                for (int q = 0; q < 12; q++) {
                    ulonglong2 v = av[q];
                    if (q & 1) {
                        a2 = fma2(wih[2 * q],     v.x, a2);
                        a3 = fma2(wih[2 * q + 1], v.y, a3);
                    } else {
                        a0 = fma2(wih[2 * q],     v.x, a0);
                        a1 = fma2(wih[2 * q + 1], v.y, a1);
                    }
                }
                a0 = fma2(wih[24],
                          reinterpret_cast<const u64*>(rbase)[24], a0);
                orow[(size_t)row * H_] =
                    pair_sum(add2(add2(a0, a1), add2(a2, a3))) + bias;
            }
        }
        __syncthreads();
        pb ^= 1;
    }
}

// ================= FC GEMM: out[n,o] = hs[n,:]·W_fc[o,:] + b_fc[o] =========
#define FC_ROWS 16
#define FC_NT   (N_TOT / FC_ROWS)
__global__ void __launch_bounds__(256) fc_kernel(
    const float* __restrict__ W_fc,
    const float* __restrict__ b_fc,
    float* __restrict__ out)
{
    __shared__ __align__(16) float hs_s[2][FC_ROWS * H_];

    const int tid = threadIdx.x;
    const int o   = tid & 63;
    const int g   = tid >> 6;
    const bool is_o = (o < O_);

    u64 wfc[58];
    float bias = 0.f;
    if (is_o) {
        const u64* p = reinterpret_cast<const u64*>(W_fc + o * H_);
        #pragma unroll
        for (int q = 0; q < 58; q++) wfc[q] = p[q];
        bias = b_fc[o];
    }

    const float* hs = g_hs;
    int tile = blockIdx.x;
    if (tile < FC_NT) {
        const float* src = hs + (size_t)tile * (FC_ROWS * H_);
        for (int i = tid; i < (FC_ROWS * H_) / 4; i += 256)
            cp16(&hs_s[0][4 * i], src + 4 * i);
    }
    CP_COMMIT();

    int pb = 0;
    for (; tile < FC_NT; tile += gridDim.x) {
        const int nxt = tile + gridDim.x;
        if (nxt < FC_NT) {
            const float* src = hs + (size_t)nxt * (FC_ROWS * H_);
            for (int i = tid; i < (FC_ROWS * H_) / 4; i += 256)
                cp16(&hs_s[pb ^ 1][4 * i], src + 4 * i);
        }
        CP_COMMIT();
        CP_WAIT(1);
        __syncthreads();

        if (is_o) {
            #pragma unroll
            for (int i = 0; i < FC_ROWS / 4; i++) {
                const int row = 4 * i + g;
                const ulonglong2* av = reinterpret_cast<const ulonglong2*>(
                    hs_s[pb] + row * H_);
                u64 a0 = 0, a1 = 0, a2 = 0, a3 = 0,
                    a4 = 0, a5 = 0, a6 = 0, a7 = 0;
                #pragma unroll
                for (int q = 0; q < 7; q++) {
                    ulonglong2 v0 = av[4 * q],     v1 = av[4 * q + 1];
                    ulonglong2 v2 = av[4 * q + 2], v3 = av[4 * q + 3];
                    a0 = fma2(wfc[8 * q],     v0.x, a0);
                    a1 = fma2(wfc[8 * q + 1], v0.y, a1);
                    a2 = fma2(wfc[8 * q + 2], v1.x, a2);
                    a3 = fma2(wfc[8 * q + 3], v1.y, a3);
                    a4 = fma2(wfc[8 * q + 4], v2.x, a4);
                    a5 = fma2(wfc[8 * q + 5], v2.y, a5);
                    a6 = fma2(wfc[8 * q + 6], v3.x, a6);
                    a7 = fma2(wfc[8 * q + 7], v3.y, a7);
                }
                { ulonglong2 v = av[28];
                  a6 = fma2(wfc[56], v.x, a6);
                  a7 = fma2(wfc[57], v.y, a7); }
                out[(size_t)(tile * FC_ROWS + row) * O_ + o] =
                    pair_sum(add2(add2(add2(a0, a1), add2(a2, a3)),
                                  add2(add2(a4, a5), add2(a6, a7)))) + bias;
            }
        }
        __syncthreads();
        pb ^= 1;
    }
}

// ================= recurrence: h(t+1) = relu(xp(t) + W_hh·h(t)) ============
// 256 CTAs x 256 threads; ONE batch row per CTA -> 2 CTAs/SM with
// independently-phased barriers (fills issue bubbles of the serial chain).
// Lane pair (2j, 2j+1) computes h[j]: half0 k[0,60), half1 k[60,116),
// partials merged via shfl.bfly(1). h tail [116,128) stays zero.
// Lanes [232,256): cp.async prefetch of xp rows (3-step lead, ring of 4).
__global__ void __launch_bounds__(256, 2) rnn_kernel(
    const float* __restrict__ W_hh)
{
    __shared__ __align__(16) float h_s[2][128];     // [pingpong][j]
    __shared__ __align__(16) float x_s[4][120];     // xp ring

    const int s    = threadIdx.x;
    const int j    = s >> 1;
    const int half = s & 1;
    const int b    = blockIdx.x;
    const bool comp   = (j < H_);
    const bool loader = (s >= 232);    // 24 lanes

    if (half == 0) { h_s[0][j] = 0.f; h_s[1][j] = 0.f; }

    u64 w[30];
    if (comp) {
        const u64* wsrc =
            reinterpret_cast<const u64*>(W_hh + j * H_ + 60 * half);
        const int nw = 30 - 2 * half;
        #pragma unroll
        for (int q = 0; q < 30; q++) w[q] = (q < nw) ? wsrc[q] : 0ull;
    }

    const float* xpb = g_xp + (size_t)b * T_ * H_;
    const int u = s - 232;

    if (loader) {
        #pragma unroll
        for (int t0 = 0; t0 < 3; t0++) {
            const float* row = xpb + (size_t)t0 * H_;
            cp16(&x_s[t0][4 * u], row + 4 * u);
            if (u < 5) cp16(&x_s[t0][4 * (u + 24)], row + 4 * (u + 24));
            CP_COMMIT();
        }
        CP_WAIT(2);    // slot 0 complete
    }
    __syncthreads();

    float* hs_ptr = g_hs + (size_t)b * T_ * H_ + j;
    int p = 0;
    for (int t = 0; t < T_; t++) {
        float partial = 0.f;
        if (comp) {
            const ulonglong2* hv =
                reinterpret_cast<const ulonglong2*>(h_s[p]) + 15 * half;
            u64 a0 = half ? 0ull : (u64)__float_as_uint(x_s[t & 3][j]);
            u64 a1 = 0, a2 = 0, a3 = 0;
            #pragma unroll
            for (int q = 0; q < 15; q++) {
                ulonglong2 v = hv[q];
                if (q & 1) {
                    a2 = fma2(w[2 * q],     v.x, a2);
                    a3 = fma2(w[2 * q + 1], v.y, a3);
                } else {
                    a0 = fma2(w[2 * q],     v.x, a0);
                    a1 = fma2(w[2 * q + 1], v.y, a1);
                }
            }
            partial = pair_sum(add2(add2(a0, a1), add2(a2, a3)));
        } else if (loader) {
            const int t3 = t + 3;
            if (t3 < T_) {
                const float* row = xpb + (size_t)t3 * H_;
                cp16(&x_s[t3 & 3][4 * u], row + 4 * u);
                if (u < 5)
                    cp16(&x_s[t3 & 3][4 * (u + 24)], row + 4 * (u + 24));
            }
            CP_COMMIT();
            CP_WAIT(2);
        }
        float other = __shfl_xor_sync(0xFFFFFFFFu, partial, 1);
        if (comp & (half == 0)) {
            float h = fmaxf(partial + other, 0.f);
            h_s[p ^ 1][j] = h;
            hs_ptr[0] = h;
            hs_ptr += H_;
        }
        __syncthreads();
        p ^= 1;
    }
}

// Probe kernel: shifts the ncu skip-window so a later capture lands on
// rnn/fc instead of xp. Deterministic, negligible cost.
__global__ void probe_kernel() {
    if (threadIdx.x == 0 && blockIdx.x == 0) g_xp[0] = 0.f;
}

// ---------------- launch ----------------
extern "C" void kernel_launch(void* const* d_in, const int* in_sizes, int n_in,
                              void* d_out, int out_size)
{
    const float* x    = (const float*)d_in[0];
    const float* W_ih = (const float*)d_in[1];
    const float* b_ih = (const float*)d_in[2];
    const float* W_hh = (const float*)d_in[3];
    const float* b_hh = (const float*)d_in[4];
    const float* W_fc = (const float*)d_in[5];
    const float* b_fc = (const float*)d_in[6];
    float* out = (float*)d_out;

    xp_kernel<<<4096, 256>>>(x, W_ih, b_ih, b_hh);
    rnn_kernel<<<B_, 256>>>(W_hh);
    fc_kernel<<<2048, 256>>>(W_fc, b_fc, out);
    probe_kernel<<<1, 32>>>();
}

// round 7
// speedup vs baseline: 2.5279x; 1.0221x over previous
#include <cuda_runtime.h>
#include <cstdint>

#define B_ 256
#define T_ 2048
#define I_ 50
#define H_ 116
#define O_ 50
#define N_TOT (B_ * T_)

typedef unsigned long long u64;

// Device scratch (static allocation = allowed)
__device__ float g_xp[(size_t)N_TOT * H_];   // input projection [N, H]
__device__ float g_hs[(size_t)N_TOT * H_];   // hidden states    [N, H]

// ---------------- packed f32x2 helpers (Blackwell) ----------------
__device__ __forceinline__ u64 fma2(u64 a, u64 b, u64 c) {
    u64 d;
    asm("fma.rn.f32x2 %0, %1, %2, %3;" : "=l"(d) : "l"(a), "l"(b), "l"(c));
    return d;
}
__device__ __forceinline__ u64 add2(u64 a, u64 b) {
    u64 d;
    asm("add.rn.f32x2 %0, %1, %2;" : "=l"(d) : "l"(a), "l"(b));
    return d;
}
__device__ __forceinline__ float pair_sum(u64 a) {
    float lo = __uint_as_float((unsigned)(a & 0xFFFFFFFFull));
    float hi = __uint_as_float((unsigned)(a >> 32));
    return lo + hi;
}
__device__ __forceinline__ void cp16(void* smem, const void* gmem) {
    unsigned s = (unsigned)__cvta_generic_to_shared(smem);
    asm volatile("cp.async.ca.shared.global [%0], [%1], 16;" :: "r"(s), "l"(gmem));
}
__device__ __forceinline__ void cp8(void* smem, const void* gmem) {
    unsigned s = (unsigned)__cvta_generic_to_shared(smem);
    asm volatile("cp.async.ca.shared.global [%0], [%1], 8;" :: "r"(s), "l"(gmem));
}
#define CP_COMMIT() asm volatile("cp.async.commit_group;")
#define CP_WAIT(n)  asm volatile("cp.async.wait_group %0;" :: "n"(n))

// ================= xp GEMM: g_xp[n,j] = x[n,:]·W_ih[j,:] + b_ih[j]+b_hh[j] ==
#define XP_ROWS 32
#define XP_RPAD 52
#define XP_NT   (N_TOT / XP_ROWS)
__global__ void __launch_bounds__(256) xp_kernel(
    const float* __restrict__ x,
    const float* __restrict__ W_ih,
    const float* __restrict__ b_ih,
    const float* __restrict__ b_hh)
{
    __shared__ __align__(16) float xs[2][XP_ROWS * XP_RPAD];

    const int tid = threadIdx.x;
    const int j   = tid & 127;
    const int r2  = tid >> 7;
    const bool is_j = (j < H_);

    u64 wih[25];
    float bias = 0.f;
    if (is_j) {
        const u64* p = reinterpret_cast<const u64*>(W_ih + j * I_);
        #pragma unroll
        for (int q = 0; q < 25; q++) wih[q] = p[q];
        bias = b_ih[j] + b_hh[j];
    }

    auto stage = [&](int tile, int buf) {
        const float* src = x + (size_t)tile * (XP_ROWS * I_);
        for (int i = tid; i < XP_ROWS * 25; i += 256) {
            int row = i / 25, c = i - 25 * row;
            cp8(&xs[buf][row * XP_RPAD + 2 * c], src + row * I_ + 2 * c);
        }
    };

    int tile = blockIdx.x;
    if (tile < XP_NT) stage(tile, 0);
    CP_COMMIT();

    int pb = 0;
    for (; tile < XP_NT; tile += gridDim.x) {
        const int nxt = tile + gridDim.x;
        if (nxt < XP_NT) stage(nxt, pb ^ 1);
        CP_COMMIT();
        CP_WAIT(1);
        __syncthreads();

        if (is_j) {
            float* orow = g_xp + (size_t)tile * XP_ROWS * H_ + j;
            #pragma unroll 2
            for (int i = 0; i < XP_ROWS / 2; i++) {
                const int row = 2 * i + r2;
                const float* rbase = xs[pb] + row * XP_RPAD;
                const ulonglong2* av =
                    reinterpret_cast<const ulonglong2*>(rbase);
                u64 a0 = 0, a1 = 0, a2 = 0, a3 = 0;
                #pragma unroll
                for (int q = 0; q < 12; q++) {
                    ulonglong2 v = av[q];
                    if (q & 1) {
                        a2 = fma2(wih[2 * q],     v.x, a2);
                        a3 = fma2(wih[2 * q + 1], v.y, a3);
                    } else {
                        a0 = fma2(wih[2 * q],     v.x, a0);
                        a1 = fma2(wih[2 * q + 1], v.y, a1);
                    }
                }
                a0 = fma2(wih[24],
                          reinterpret_cast<const u64*>(rbase)[24], a0);
                orow[(size_t)row * H_] =
                    pair_sum(add2(add2(a0, a1), add2(a2, a3))) + bias;
            }
        }
        __syncthreads();
        pb ^= 1;
    }
}

// ================= FC GEMM: out[n,o] = hs[n,:]·W_fc[o,:] + b_fc[o] =========
#define FC_ROWS 16
#define FC_NT   (N_TOT / FC_ROWS)
__global__ void __launch_bounds__(256) fc_kernel(
    const float* __restrict__ W_fc,
    const float* __restrict__ b_fc,
    float* __restrict__ out)
{
    __shared__ __align__(16) float hs_s[2][FC_ROWS * H_];

    const int tid = threadIdx.x;
    const int o   = tid & 63;
    const int g   = tid >> 6;
    const bool is_o = (o < O_);

    u64 wfc[58];
    float bias = 0.f;
    if (is_o) {
        const u64* p = reinterpret_cast<const u64*>(W_fc + o * H_);
        #pragma unroll
        for (int q = 0; q < 58; q++) wfc[q] = p[q];
        bias = b_fc[o];
    }

    const float* hs = g_hs;
    int tile = blockIdx.x;
    if (tile < FC_NT) {
        const float* src = hs + (size_t)tile * (FC_ROWS * H_);
        for (int i = tid; i < (FC_ROWS * H_) / 4; i += 256)
            cp16(&hs_s[0][4 * i], src + 4 * i);
    }
    CP_COMMIT();

    int pb = 0;
    for (; tile < FC_NT; tile += gridDim.x) {
        const int nxt = tile + gridDim.x;
        if (nxt < FC_NT) {
            const float* src = hs + (size_t)nxt * (FC_ROWS * H_);
            for (int i = tid; i < (FC_ROWS * H_) / 4; i += 256)
                cp16(&hs_s[pb ^ 1][4 * i], src + 4 * i);
        }
        CP_COMMIT();
        CP_WAIT(1);
        __syncthreads();

        if (is_o) {
            #pragma unroll
            for (int i = 0; i < FC_ROWS / 4; i++) {
                const int row = 4 * i + g;
                const ulonglong2* av = reinterpret_cast<const ulonglong2*>(
                    hs_s[pb] + row * H_);
                u64 a0 = 0, a1 = 0, a2 = 0, a3 = 0,
                    a4 = 0, a5 = 0, a6 = 0, a7 = 0;
                #pragma unroll
                for (int q = 0; q < 7; q++) {
                    ulonglong2 v0 = av[4 * q],     v1 = av[4 * q + 1];
                    ulonglong2 v2 = av[4 * q + 2], v3 = av[4 * q + 3];
                    a0 = fma2(wfc[8 * q],     v0.x, a0);
                    a1 = fma2(wfc[8 * q + 1], v0.y, a1);
                    a2 = fma2(wfc[8 * q + 2], v1.x, a2);
                    a3 = fma2(wfc[8 * q + 3], v1.y, a3);
                    a4 = fma2(wfc[8 * q + 4], v2.x, a4);
                    a5 = fma2(wfc[8 * q + 5], v2.y, a5);
                    a6 = fma2(wfc[8 * q + 6], v3.x, a6);
                    a7 = fma2(wfc[8 * q + 7], v3.y, a7);
                }
                { ulonglong2 v = av[28];
                  a6 = fma2(wfc[56], v.x, a6);
                  a7 = fma2(wfc[57], v.y, a7); }
                out[(size_t)(tile * FC_ROWS + row) * O_ + o] =
                    pair_sum(add2(add2(add2(a0, a1), add2(a2, a3)),
                                  add2(add2(a4, a5), add2(a6, a7)))) + bias;
            }
        }
        __syncthreads();
        pb ^= 1;
    }
}

// ================= recurrence: h(t+1) = relu(xp(t) + W_hh·h(t)) ============
// 256 CTAs x 288 threads (9 warps); ONE batch row per CTA, 2 CTAs/SM.
// Warps 0-7 (lanes 0-231): lane pair (2j,2j+1) computes h[j]; half0 k[0,60),
// half1 k[60,116); partials merged via shfl.bfly(1). h tail stays zero.
// Warp 8 (lanes 256+): DEDICATED loader warp — cp.async prefetch of xp rows,
// 4-step lead, ring of 8. cp.async.wait_group stalls ONLY this warp, so the
// per-step barrier never serializes compute behind DRAM latency or cp issue.
__global__ void __launch_bounds__(288, 2) rnn_kernel(
    const float* __restrict__ W_hh)
{
    __shared__ __align__(16) float h_s[2][128];     // [pingpong][j]
    __shared__ __align__(16) float x_s[8][120];     // xp ring (slot = t&7)

    const int s    = threadIdx.x;
    const int j    = s >> 1;
    const int half = s & 1;
    const int b    = blockIdx.x;
    const bool comp   = (s < 232);
    const bool loader = (s >= 256);    // warp 8

    if (s < 256 && half == 0) { h_s[0][j] = 0.f; h_s[1][j] = 0.f; }

    u64 w[30];
    if (comp) {
        const u64* wsrc =
            reinterpret_cast<const u64*>(W_hh + j * H_ + 60 * half);
        const int nw = 30 - 2 * half;
        #pragma unroll
        for (int q = 0; q < 30; q++) w[q] = (q < nw) ? wsrc[q] : 0ull;
    }

    const float* xpb = g_xp + (size_t)b * T_ * H_;
    const int u = s - 256;             // loader lane 0..31 (0..28 active)

    if (loader) {
        #pragma unroll
        for (int t0 = 0; t0 < 4; t0++) {
            if (u < 29) cp16(&x_s[t0][4 * u], xpb + (size_t)t0 * H_ + 4 * u);
            CP_COMMIT();
        }
        CP_WAIT(3);    // slot 0 complete
    }
    __syncthreads();

    float* hs_ptr = g_hs + (size_t)b * T_ * H_ + j;
    int p = 0;
    for (int t = 0; t < T_; t++) {
        float partial = 0.f;
        if (comp) {
            const ulonglong2* hv =
                reinterpret_cast<const ulonglong2*>(h_s[p]) + 15 * half;
            u64 a0 = half ? 0ull : (u64)__float_as_uint(x_s[t & 7][j]);
            u64 a1 = 0, a2 = 0, a3 = 0;
            #pragma unroll
            for (int q = 0; q < 15; q++) {
                ulonglong2 v = hv[q];
                if (q & 1) {
                    a2 = fma2(w[2 * q],     v.x, a2);
                    a3 = fma2(w[2 * q + 1], v.y, a3);
                } else {
                    a0 = fma2(w[2 * q],     v.x, a0);
                    a1 = fma2(w[2 * q + 1], v.y, a1);
                }
            }
            partial = pair_sum(add2(add2(a0, a1), add2(a2, a3)));
        } else if (loader) {
            const int t4 = t + 4;
            if (t4 < T_ && u < 29)
                cp16(&x_s[t4 & 7][4 * u], xpb + (size_t)t4 * H_ + 4 * u);
            CP_COMMIT();
            CP_WAIT(3);    // slot t+1 complete (3-step slack hides DRAM)
        }
        float other = __shfl_xor_sync(0xFFFFFFFFu, partial, 1);
        if (comp & (half == 0)) {
            float h = fmaxf(partial + other, 0.f);
            h_s[p ^ 1][j] = h;
            hs_ptr[0] = h;
            hs_ptr += H_;
        }
        __syncthreads();
        p ^= 1;
    }
}

// Probe kernel: occupies an ncu capture slot; also shifts fc into the slot
// that was captured last round. Deterministic, negligible cost.
__global__ void probe_kernel() {
    if (threadIdx.x == 0 && blockIdx.x == 0) g_xp[0] = g_xp[0];
}

// ---------------- launch ----------------
extern "C" void kernel_launch(void* const* d_in, const int* in_sizes, int n_in,
                              void* d_out, int out_size)
{
    const float* x    = (const float*)d_in[0];
    const float* W_ih = (const float*)d_in[1];
    const float* b_ih = (const float*)d_in[2];
    const float* W_hh = (const float*)d_in[3];
    const float* b_hh = (const float*)d_in[4];
    const float* W_fc = (const float*)d_in[5];
    const float* b_fc = (const float*)d_in[6];
    float* out = (float*)d_out;

    xp_kernel<<<4096, 256>>>(x, W_ih, b_ih, b_hh);
    rnn_kernel<<<B_, 288>>>(W_hh);
    probe_kernel<<<1, 32>>>();
    fc_kernel<<<2048, 256>>>(W_fc, b_fc, out);
}

// round 8
// speedup vs baseline: 3.0224x; 1.1956x over previous
#include <cuda_runtime.h>
#include <cstdint>

#define B_ 256
#define T_ 2048
#define I_ 50
#define H_ 116
#define O_ 50
#define N_TOT (B_ * T_)

typedef unsigned long long u64;

// Device scratch (static allocation = allowed)
__device__ float g_xp[(size_t)N_TOT * H_];   // input projection [N, H]
__device__ float g_hs[(size_t)N_TOT * H_];   // hidden states    [N, H]

// ---------------- packed f32x2 helpers (Blackwell) ----------------
__device__ __forceinline__ u64 fma2(u64 a, u64 b, u64 c) {
    u64 d;
    asm("fma.rn.f32x2 %0, %1, %2, %3;" : "=l"(d) : "l"(a), "l"(b), "l"(c));
    return d;
}
__device__ __forceinline__ u64 add2(u64 a, u64 b) {
    u64 d;
    asm("add.rn.f32x2 %0, %1, %2;" : "=l"(d) : "l"(a), "l"(b));
    return d;
}
__device__ __forceinline__ float pair_sum(u64 a) {
    float lo = __uint_as_float((unsigned)(a & 0xFFFFFFFFull));
    float hi = __uint_as_float((unsigned)(a >> 32));
    return lo + hi;
}
__device__ __forceinline__ void cp16(void* smem, const void* gmem) {
    unsigned s = (unsigned)__cvta_generic_to_shared(smem);
    asm volatile("cp.async.ca.shared.global [%0], [%1], 16;" :: "r"(s), "l"(gmem));
}
__device__ __forceinline__ void cp8(void* smem, const void* gmem) {
    unsigned s = (unsigned)__cvta_generic_to_shared(smem);
    asm volatile("cp.async.ca.shared.global [%0], [%1], 8;" :: "r"(s), "l"(gmem));
}
#define CP_COMMIT() asm volatile("cp.async.commit_group;")
#define CP_WAIT(n)  asm volatile("cp.async.wait_group %0;" :: "n"(n))

// ================= xp GEMM: g_xp[n,j] = x[n,:]·W_ih[j,:] + b_ih[j]+b_hh[j] ==
#define XP_ROWS 32
#define XP_RPAD 52
#define XP_NT   (N_TOT / XP_ROWS)
__global__ void __launch_bounds__(256) xp_kernel(
    const float* __restrict__ x,
    const float* __restrict__ W_ih,
    const float* __restrict__ b_ih,
    const float* __restrict__ b_hh)
{
    __shared__ __align__(16) float xs[2][XP_ROWS * XP_RPAD];

    const int tid = threadIdx.x;
    const int j   = tid & 127;
    const int r2  = tid >> 7;
    const bool is_j = (j < H_);

    u64 wih[25];
    float bias = 0.f;
    if (is_j) {
        const u64* p = reinterpret_cast<const u64*>(W_ih + j * I_);
        #pragma unroll
        for (int q = 0; q < 25; q++) wih[q] = p[q];
        bias = b_ih[j] + b_hh[j];
    }

    auto stage = [&](int tile, int buf) {
        const float* src = x + (size_t)tile * (XP_ROWS * I_);
        for (int i = tid; i < XP_ROWS * 25; i += 256) {
            int row = i / 25, c = i - 25 * row;
            cp8(&xs[buf][row * XP_RPAD + 2 * c], src + row * I_ + 2 * c);
        }
    };

    int tile = blockIdx.x;
    if (tile < XP_NT) stage(tile, 0);
    CP_COMMIT();

    int pb = 0;
    for (; tile < XP_NT; tile += gridDim.x) {
        const int nxt = tile + gridDim.x;
        if (nxt < XP_NT) stage(nxt, pb ^ 1);
        CP_COMMIT();
        CP_WAIT(1);
        __syncthreads();

        if (is_j) {
            float* orow = g_xp + (size_t)tile * XP_ROWS * H_ + j;
            #pragma unroll 2
            for (int i = 0; i < XP_ROWS / 2; i++) {
                const int row = 2 * i + r2;
                const float* rbase = xs[pb] + row * XP_RPAD;
                const ulonglong2* av =
                    reinterpret_cast<const ulonglong2*>(rbase);
                u64 a0 = 0, a1 = 0, a2 = 0, a3 = 0;
                #pragma unroll
                for (int q = 0; q < 12; q++) {
                    ulonglong2 v = av[q];
                    if (q & 1) {
                        a2 = fma2(wih[2 * q],     v.x, a2);
                        a3 = fma2(wih[2 * q + 1], v.y, a3);
                    } else {
                        a0 = fma2(wih[2 * q],     v.x, a0);
                        a1 = fma2(wih[2 * q + 1], v.y, a1);
                    }
                }
                a0 = fma2(wih[24],
                          reinterpret_cast<const u64*>(rbase)[24], a0);
                orow[(size_t)row * H_] =
                    pair_sum(add2(add2(a0, a1), add2(a2, a3))) + bias;
            }
        }
        __syncthreads();
        pb ^= 1;
    }
}

// ================= FC GEMM: out[n,o] = hs[n,:]·W_fc[o,:] + b_fc[o] =========
// k-split lane pairs: lanes (2o, 2o+1) hold half of W_fc row o in regs
// (~95 regs/thread -> 2 CTAs/SM), partials merged via shfl.bfly(1).
#define FC_ROWS 16
#define FC_NT   (N_TOT / FC_ROWS)
__global__ void __launch_bounds__(256, 2) fc_kernel(
    const float* __restrict__ W_fc,
    const float* __restrict__ b_fc,
    float* __restrict__ out)
{
    __shared__ __align__(16) float hs_s[2][FC_ROWS * H_ + 4];  // +4: half1 tail

    const int tid  = threadIdx.x;
    const int o2   = tid & 127;
    const int o    = o2 >> 1;          // 0..63, active < 50
    const int half = o2 & 1;
    const int g    = tid >> 7;         // row parity group
    const bool is_o = (o < O_);

    // half0 holds k[0,60) (30 u64), half1 holds k[60,116) (28 u64, 2 zero)
    u64 w[30];
    #pragma unroll
    for (int q = 0; q < 30; q++) w[q] = 0ull;
    float bias = 0.f;
    if (is_o) {
        const u64* ws =
            reinterpret_cast<const u64*>(W_fc + o * H_ + 60 * half);
        const int nw = 30 - 2 * half;
        #pragma unroll
        for (int q = 0; q < 30; q++) if (q < nw) w[q] = ws[q];
        bias = b_fc[o];
    }

    const float* hs = g_hs;
    int tile = blockIdx.x;
    if (tile < FC_NT) {
        const float* src = hs + (size_t)tile * (FC_ROWS * H_);
        for (int i = tid; i < (FC_ROWS * H_) / 4; i += 256)
            cp16(&hs_s[0][4 * i], src + 4 * i);
    }
    CP_COMMIT();

    int pb = 0;
    for (; tile < FC_NT; tile += gridDim.x) {
        const int nxt = tile + gridDim.x;
        if (nxt < FC_NT) {
            const float* src = hs + (size_t)nxt * (FC_ROWS * H_);
            for (int i = tid; i < (FC_ROWS * H_) / 4; i += 256)
                cp16(&hs_s[pb ^ 1][4 * i], src + 4 * i);
        }
        CP_COMMIT();
        CP_WAIT(1);
        __syncthreads();

        #pragma unroll
        for (int i = 0; i < FC_ROWS / 2; i++) {
            const int row = 2 * i + g;
            const ulonglong2* hv = reinterpret_cast<const ulonglong2*>(
                hs_s[pb] + row * H_ + 60 * half);   // 16B-aligned both halves
            u64 a0 = 0, a1 = 0, a2 = 0, a3 = 0;
            #pragma unroll
            for (int q = 0; q < 15; q++) {
                ulonglong2 v = hv[q];
                if (q & 1) {
                    a2 = fma2(w[2 * q],     v.x, a2);
                    a3 = fma2(w[2 * q + 1], v.y, a3);
                } else {
                    a0 = fma2(w[2 * q],     v.x, a0);
                    a1 = fma2(w[2 * q + 1], v.y, a1);
                }
            }
            float part = pair_sum(add2(add2(a0, a1), add2(a2, a3)));
            float oth  = __shfl_xor_sync(0xFFFFFFFFu, part, 1);
            if (is_o && half == 0)
                out[(size_t)(tile * FC_ROWS + row) * O_ + o] =
                    part + oth + bias;
        }
        __syncthreads();
        pb ^= 1;
    }
}

// ================= recurrence: h(t+1) = relu(xp(t) + W_hh·h(t)) ============
// 256 CTAs x 128 threads (4 warps), 1 row/CTA, 2 CTAs/SM. Thread j holds the
// FULL W_hh row j in registers (116 regs). h(t) read via perfect-broadcast
// LDS.128 (all lanes same address). xp prefetched 2 steps ahead via __ldg
// into rotating registers — no loader warp, no shfl, one 4-warp barrier.
__global__ void __launch_bounds__(128, 2) rnn_kernel(
    const float* __restrict__ W_hh)
{
    __shared__ __align__(16) float h_s[2][120];   // ping-pong, 116 used

    const int j = threadIdx.x;
    const int b = blockIdx.x;
    const bool comp = (j < H_);

    if (j < 120) { h_s[0][j] = 0.f; h_s[1][j] = 0.f; }

    u64 w[58];
    if (comp) {
        const u64* ws = reinterpret_cast<const u64*>(W_hh + j * H_);
        #pragma unroll
        for (int q = 0; q < 58; q++) w[q] = ws[q];
    }

    const float* xpb = g_xp + (size_t)b * T_ * H_ + j;
    float xpr0 = 0.f, xpr1 = 0.f;
    if (comp) { xpr0 = __ldg(xpb); xpr1 = __ldg(xpb + H_); }
    __syncthreads();

    float* hs_ptr = g_hs + (size_t)b * T_ * H_ + j;
    int p = 0;

#define RNN_STEP(XPR, TNEXT)                                                 \
    {                                                                        \
        u64 a0 = (u64)__float_as_uint(XPR);        /* consume xp(t) */       \
        if (comp && (TNEXT) < T_)                  /* refill, 2-step slack */\
            XPR = __ldg(xpb + (size_t)(TNEXT) * H_);                         \
        u64 a1 = 0, a2 = 0, a3 = 0;                                          \
        const ulonglong2* hv =                                               \
            reinterpret_cast<const ulonglong2*>(h_s[p]);                     \
        _Pragma("unroll")                                                    \
        for (int q = 0; q < 29; q++) {                                       \
            ulonglong2 v = hv[q];                                            \
            if (q & 1) { a2 = fma2(w[2 * q],     v.x, a2);                   \
                         a3 = fma2(w[2 * q + 1], v.y, a3); }                 \
            else       { a0 = fma2(w[2 * q],     v.x, a0);                   \
                         a1 = fma2(w[2 * q + 1], v.y, a1); }                 \
        }                                                                    \
        if (comp) {                                                          \
            float h = fmaxf(                                                 \
                pair_sum(add2(add2(a0, a1), add2(a2, a3))), 0.f);            \
            h_s[p ^ 1][j] = h;                                               \
            hs_ptr[0] = h; hs_ptr += H_;                                     \
        }                                                                    \
        __syncthreads();                                                     \
        p ^= 1;                                                              \
    }

    for (int t = 0; t < T_; t += 2) {
        RNN_STEP(xpr0, t + 2)
        RNN_STEP(xpr1, t + 3)
    }
#undef RNN_STEP
}

// Probe kernels: occupy ncu capture slots so slot 4 = rnn_kernel.
__global__ void probe_kernel() {
    if (threadIdx.x == 0 && blockIdx.x == 0) g_xp[0] = g_xp[0];
}

// ---------------- launch ----------------
extern "C" void kernel_launch(void* const* d_in, const int* in_sizes, int n_in,
                              void* d_out, int out_size)
{
    const float* x    = (const float*)d_in[0];
    const float* W_ih = (const float*)d_in[1];
    const float* b_ih = (const float*)d_in[2];
    const float* W_hh = (const float*)d_in[3];
    const float* b_hh = (const float*)d_in[4];
    const float* W_fc = (const float*)d_in[5];
    const float* b_fc = (const float*)d_in[6];
    float* out = (float*)d_out;

    xp_kernel<<<4096, 256>>>(x, W_ih, b_ih, b_hh);
    probe_kernel<<<1, 32>>>();
    probe_kernel<<<1, 32>>>();
    rnn_kernel<<<B_, 128>>>(W_hh);
    fc_kernel<<<2048, 256>>>(W_fc, b_fc, out);
}